// round 4
// baseline (speedup 1.0000x reference)
#include <cuda_runtime.h>

// GNN_82592221102580: per batch b (nc = 4096):
//   E[k][i]   = exp(X[b][k][i])                       (softmax numerator, col-normalized)
//   S[i]      = sum_k E[k][i];  A[i][k] = E[k][i]/S[i]
//   Xn[k][j]  = a2[j]*(X[b][k][j]-mean_k)/(std_k(ddof=1)+1e-6) + b2[j]
//   node      = A @ Xn            (64x64)
//   out[b]    = relu(node @ W)    (64x64)
//
// One CTA of 256 threads per batch tile. Two recycled smem buffers.

#define SMEM_STRIDE 68   // 64 + 4 pad: keeps float4 (16B) alignment per row, de-conflicts banks

__global__ __launch_bounds__(256) void gnn_fused_kernel(
    const float* __restrict__ X,
    const float* __restrict__ W,
    const float* __restrict__ a2,
    const float* __restrict__ b2,
    float* __restrict__ out)
{
    __shared__ __align__(16) float B0[64 * SMEM_STRIDE]; // Xn, later W
    __shared__ __align__(16) float B1[64 * SMEM_STRIDE]; // E,  later node^T
    __shared__ __align__(16) float a2s[64];
    __shared__ __align__(16) float b2s[64];
    __shared__ __align__(16) float Sp[4 * 64];
    __shared__ __align__(16) float Sinv[64];

    const int t = threadIdx.x;
    const float* __restrict__ Xb = X + (size_t)blockIdx.x * 4096u;
    float* __restrict__ Ob = out + (size_t)blockIdx.x * 4096u;

    if (t < 64) { a2s[t] = a2[t]; b2s[t] = b2[t]; }

    // ---- Pass 1: load 16 X elems/thread (one 64B chunk), emit E, row stats ----
    const int r     = t >> 2;        // row 0..63
    const int part  = t & 3;         // quarter of the row
    const int cbase = part * 16;

    float4 xv[4];
#pragma unroll
    for (int q = 0; q < 4; q++)
        xv[q] = *(const float4*)(Xb + r * 64 + cbase + 4 * q);

    float s = 0.f, ss = 0.f;
#pragma unroll
    for (int q = 0; q < 4; q++) {
        float4 v = xv[q];
        s  += v.x + v.y + v.z + v.w;
        ss += v.x * v.x + v.y * v.y + v.z * v.z + v.w * v.w;
        float4 e;
        e.x = __expf(v.x); e.y = __expf(v.y);
        e.z = __expf(v.z); e.w = __expf(v.w);
        *(float4*)&B1[r * SMEM_STRIDE + cbase + 4 * q] = e;
    }
    // reduce sum / sumsq across the 4 lanes owning this row
    s  += __shfl_xor_sync(0xFFFFFFFFu, s, 1);
    s  += __shfl_xor_sync(0xFFFFFFFFu, s, 2);
    ss += __shfl_xor_sync(0xFFFFFFFFu, ss, 1);
    ss += __shfl_xor_sync(0xFFFFFFFFu, ss, 2);

    const float mean = s * (1.0f / 64.0f);
    float var = (ss - 64.0f * mean * mean) * (1.0f / 63.0f);
    var = fmaxf(var, 0.0f);
    const float rinv = 1.0f / (sqrtf(var) + 1e-6f);

    __syncthreads();   // a2s/b2s ready; B1 (E) fully written

    // ---- Xn into B0 (same 16 elements, still in registers) ----
#pragma unroll
    for (int q = 0; q < 4; q++) {
        float4 v = xv[q];
        const int j = cbase + 4 * q;
        float4 xn;
        xn.x = a2s[j + 0] * (v.x - mean) * rinv + b2s[j + 0];
        xn.y = a2s[j + 1] * (v.y - mean) * rinv + b2s[j + 1];
        xn.z = a2s[j + 2] * (v.z - mean) * rinv + b2s[j + 2];
        xn.w = a2s[j + 3] * (v.w - mean) * rinv + b2s[j + 3];
        *(float4*)&B0[r * SMEM_STRIDE + j] = xn;
    }

    // ---- Column partial sums of E (conflict-free: lanes span contiguous cols) ----
    {
        const int i = t & 63, p = t >> 6;
        float cs = 0.f;
#pragma unroll
        for (int k = 0; k < 16; k++)
            cs += B1[(p * 16 + k) * SMEM_STRIDE + i];
        Sp[p * 64 + i] = cs;
    }
    __syncthreads();
    if (t < 64)
        Sinv[t] = 1.0f / (Sp[t] + Sp[64 + t] + Sp[128 + t] + Sp[192 + t]);
    __syncthreads();

    // ---- GEMM1: node[i][j] = Sinv[i] * sum_k E[k][i] * Xn[k][j] ----
    const int ty = t >> 4, tx = t & 15;
    const int i0 = ty * 4, j0 = tx * 4;

    float acc[4][4];
#pragma unroll
    for (int ii = 0; ii < 4; ii++)
#pragma unroll
        for (int jj = 0; jj < 4; jj++) acc[ii][jj] = 0.f;

#pragma unroll 8
    for (int k = 0; k < 64; k++) {
        const float4 a = *(const float4*)&B1[k * SMEM_STRIDE + i0]; // E[k][i0..]
        const float4 b = *(const float4*)&B0[k * SMEM_STRIDE + j0]; // Xn[k][j0..]
        acc[0][0] += a.x * b.x; acc[0][1] += a.x * b.y; acc[0][2] += a.x * b.z; acc[0][3] += a.x * b.w;
        acc[1][0] += a.y * b.x; acc[1][1] += a.y * b.y; acc[1][2] += a.y * b.z; acc[1][3] += a.y * b.w;
        acc[2][0] += a.z * b.x; acc[2][1] += a.z * b.y; acc[2][2] += a.z * b.z; acc[2][3] += a.z * b.w;
        acc[3][0] += a.w * b.x; acc[3][1] += a.w * b.y; acc[3][2] += a.w * b.z; acc[3][3] += a.w * b.w;
    }
    const float4 sv = *(const float4*)&Sinv[i0];

    __syncthreads();   // all reads of E/Xn complete; buffers can be recycled

    // node^T into B1: nodeT[j][i] = Sinv[i]*acc
#pragma unroll
    for (int jj = 0; jj < 4; jj++) {
        float4 v;
        v.x = acc[0][jj] * sv.x;
        v.y = acc[1][jj] * sv.y;
        v.z = acc[2][jj] * sv.z;
        v.w = acc[3][jj] * sv.w;
        *(float4*)&B1[(j0 + jj) * SMEM_STRIDE + i0] = v;
    }
    // W into B0 (L2-hot: every CTA reads the same 16 KB)
#pragma unroll
    for (int q = 0; q < 4; q++) {
        const float4 wv = *(const float4*)(W + r * 64 + cbase + 4 * q);
        *(float4*)&B0[r * SMEM_STRIDE + cbase + 4 * q] = wv;
    }
    __syncthreads();

    // ---- GEMM2: out[i][j] = relu( sum_k nodeT[k][i] * W[k][j] ) ----
#pragma unroll
    for (int ii = 0; ii < 4; ii++)
#pragma unroll
        for (int jj = 0; jj < 4; jj++) acc[ii][jj] = 0.f;

#pragma unroll 8
    for (int k = 0; k < 64; k++) {
        const float4 a = *(const float4*)&B1[k * SMEM_STRIDE + i0]; // nodeT[k][i0..]
        const float4 b = *(const float4*)&B0[k * SMEM_STRIDE + j0]; // W[k][j0..]
        acc[0][0] += a.x * b.x; acc[0][1] += a.x * b.y; acc[0][2] += a.x * b.z; acc[0][3] += a.x * b.w;
        acc[1][0] += a.y * b.x; acc[1][1] += a.y * b.y; acc[1][2] += a.y * b.z; acc[1][3] += a.y * b.w;
        acc[2][0] += a.z * b.x; acc[2][1] += a.z * b.y; acc[2][2] += a.z * b.z; acc[2][3] += a.z * b.w;
        acc[3][0] += a.w * b.x; acc[3][1] += a.w * b.y; acc[3][2] += a.w * b.z; acc[3][3] += a.w * b.w;
    }

#pragma unroll
    for (int ii = 0; ii < 4; ii++) {
        float4 o;
        o.x = fmaxf(acc[ii][0], 0.0f);
        o.y = fmaxf(acc[ii][1], 0.0f);
        o.z = fmaxf(acc[ii][2], 0.0f);
        o.w = fmaxf(acc[ii][3], 0.0f);
        *(float4*)(Ob + (i0 + ii) * 64 + j0) = o;
    }
}

extern "C" void kernel_launch(void* const* d_in, const int* in_sizes, int n_in,
                              void* d_out, int out_size) {
    const float* X  = (const float*)d_in[0];
    const float* W  = (const float*)d_in[1];
    const float* a2 = (const float*)d_in[2];
    const float* b2 = (const float*)d_in[3];
    float* out = (float*)d_out;

    const int nc = in_sizes[0] / 4096;   // 16*256 = 4096 batch tiles of 64x64
    gnn_fused_kernel<<<nc, 256>>>(X, W, a2, b2, out);
}

// round 6
// speedup vs baseline: 1.3889x; 1.3889x over previous
#include <cuda_runtime.h>
#include <cstdint>

// GNN_82592221102580 — fused per 64x64 batch tile (nc = 4096):
//   E = exp(X); Sinv[i] = 1/sum_k E[k][i]
//   Xn = LayerNorm(X) (ddof=1)
//   node[i][j] = Sinv[i] * sum_k E[k][i]*Xn[k][j]      <- tensor cores (tf32)
//   out = relu(node @ W)                               <- tensor cores (tf32)
// One CTA (256 thr, 8 warps) per tile. mma.sync.m16n8k8 tf32 (baseline PTX,
// works on plain sm_103 target — tcgen05 'a'-features are unavailable here).

#define SMEM_STRIDE 68   // 64+4 pad: float4 aligned, de-conflicts strided access

__device__ __forceinline__ float f2tf32(float f) {
    uint32_t o;
    asm("cvt.rna.tf32.f32 %0, %1;" : "=r"(o) : "f"(f));
    return __uint_as_float(o);
}

__device__ __forceinline__ void mma_tf32(float d[4], const uint32_t a[4], const uint32_t b[2]) {
    asm volatile(
        "mma.sync.aligned.m16n8k8.row.col.f32.tf32.tf32.f32 "
        "{%0,%1,%2,%3}, {%4,%5,%6,%7}, {%8,%9}, {%0,%1,%2,%3};"
        : "+f"(d[0]), "+f"(d[1]), "+f"(d[2]), "+f"(d[3])
        : "r"(a[0]), "r"(a[1]), "r"(a[2]), "r"(a[3]), "r"(b[0]), "r"(b[1]));
}

__global__ __launch_bounds__(256) void gnn_fused_kernel(
    const float* __restrict__ X,
    const float* __restrict__ W,
    const float* __restrict__ a2,
    const float* __restrict__ b2,
    float* __restrict__ out)
{
    __shared__ __align__(16) float B0[64 * SMEM_STRIDE]; // Xn (tf32), later W (tf32)
    __shared__ __align__(16) float B1[64 * SMEM_STRIDE]; // E (tf32), later node (tf32)
    __shared__ __align__(16) float a2s[64];
    __shared__ __align__(16) float b2s[64];
    __shared__ __align__(16) float Sp[4 * 64];
    __shared__ __align__(16) float Sinv[64];

    const int t = threadIdx.x;
    const float* __restrict__ Xb = X + (size_t)blockIdx.x * 4096u;
    float* __restrict__ Ob = out + (size_t)blockIdx.x * 4096u;

    if (t < 64) { a2s[t] = a2[t]; b2s[t] = b2[t]; }

    // ---- Phase 1: load 16 X elems/thread, E (tf32) -> B1, row stats ----
    const int r     = t >> 2;
    const int part  = t & 3;
    const int cbase = part * 16;

    float4 xv[4];
#pragma unroll
    for (int q = 0; q < 4; q++)
        xv[q] = *(const float4*)(Xb + r * 64 + cbase + 4 * q);

    float s = 0.f, ss = 0.f;
#pragma unroll
    for (int q = 0; q < 4; q++) {
        float4 v = xv[q];
        s  += v.x + v.y + v.z + v.w;
        ss += v.x * v.x + v.y * v.y + v.z * v.z + v.w * v.w;
        float4 e;
        e.x = f2tf32(__expf(v.x)); e.y = f2tf32(__expf(v.y));
        e.z = f2tf32(__expf(v.z)); e.w = f2tf32(__expf(v.w));
        *(float4*)&B1[r * SMEM_STRIDE + cbase + 4 * q] = e;
    }
    s  += __shfl_xor_sync(0xFFFFFFFFu, s, 1);
    s  += __shfl_xor_sync(0xFFFFFFFFu, s, 2);
    ss += __shfl_xor_sync(0xFFFFFFFFu, ss, 1);
    ss += __shfl_xor_sync(0xFFFFFFFFu, ss, 2);

    const float mean = s * (1.0f / 64.0f);
    float var = (ss - 64.0f * mean * mean) * (1.0f / 63.0f);
    var = fmaxf(var, 0.0f);
    const float rinv = 1.0f / (sqrtf(var) + 1e-6f);

    __syncthreads();   // a2s/b2s ready; B1 (E) fully written

    // ---- Xn (tf32) -> B0 ----
#pragma unroll
    for (int q = 0; q < 4; q++) {
        float4 v = xv[q];
        const int j = cbase + 4 * q;
        float4 xn;
        xn.x = f2tf32(a2s[j + 0] * (v.x - mean) * rinv + b2s[j + 0]);
        xn.y = f2tf32(a2s[j + 1] * (v.y - mean) * rinv + b2s[j + 1]);
        xn.z = f2tf32(a2s[j + 2] * (v.z - mean) * rinv + b2s[j + 2]);
        xn.w = f2tf32(a2s[j + 3] * (v.w - mean) * rinv + b2s[j + 3]);
        *(float4*)&B0[r * SMEM_STRIDE + j] = xn;
    }

    // ---- Column sums of E -> Sinv ----
    {
        const int i = t & 63, p = t >> 6;
        float cs = 0.f;
#pragma unroll
        for (int k = 0; k < 16; k++)
            cs += B1[(p * 16 + k) * SMEM_STRIDE + i];
        Sp[p * 64 + i] = cs;
    }
    __syncthreads();
    if (t < 64)
        Sinv[t] = 1.0f / (Sp[t] + Sp[64 + t] + Sp[128 + t] + Sp[192 + t]);
    __syncthreads();

    // ---- Warp tiling: warp w owns rows [16*(w&3), +16), cols [32*(w>>2), +32) ----
    const int warp = t >> 5;
    const int lane = t & 31;
    const int g  = lane >> 2;          // group id  (0..7)
    const int tg = lane & 3;           // thread-in-group (0..3)
    const int i0 = (warp & 3) * 16;
    const int j0 = (warp >> 2) * 32;

    const uint32_t* __restrict__ B0u = (const uint32_t*)B0;
    const uint32_t* __restrict__ B1u = (const uint32_t*)B1;

    float acc[4][4];
#pragma unroll
    for (int nt = 0; nt < 4; nt++)
#pragma unroll
        for (int e = 0; e < 4; e++) acc[nt][e] = 0.f;

    // ---- GEMM1: node_u[i][j] = sum_k E[k][i] * Xn[k][j]  (A-op = E^T read) ----
#pragma unroll
    for (int kk = 0; kk < 8; kk++) {
        const int k = kk * 8;
        uint32_t a[4];
        a[0] = B1u[(k + tg)     * SMEM_STRIDE + i0 + g];
        a[1] = B1u[(k + tg)     * SMEM_STRIDE + i0 + g + 8];
        a[2] = B1u[(k + tg + 4) * SMEM_STRIDE + i0 + g];
        a[3] = B1u[(k + tg + 4) * SMEM_STRIDE + i0 + g + 8];
#pragma unroll
        for (int nt = 0; nt < 4; nt++) {
            uint32_t b[2];
            b[0] = B0u[(k + tg)     * SMEM_STRIDE + j0 + 8 * nt + g];
            b[1] = B0u[(k + tg + 4) * SMEM_STRIDE + j0 + 8 * nt + g];
            mma_tf32(acc[nt], a, b);
        }
    }

    // scale rows by Sinv
    const float s0 = Sinv[i0 + g];
    const float s1 = Sinv[i0 + g + 8];

    __syncthreads();   // all reads of E/Xn done; recycle buffers

    // node (tf32) -> B1 row-major; W (tf32) -> B0
#pragma unroll
    for (int nt = 0; nt < 4; nt++) {
        float2 lo, hi;
        lo.x = f2tf32(acc[nt][0] * s0); lo.y = f2tf32(acc[nt][1] * s0);
        hi.x = f2tf32(acc[nt][2] * s1); hi.y = f2tf32(acc[nt][3] * s1);
        *(float2*)&B1[(i0 + g)     * SMEM_STRIDE + j0 + 8 * nt + 2 * tg] = lo;
        *(float2*)&B1[(i0 + g + 8) * SMEM_STRIDE + j0 + 8 * nt + 2 * tg] = hi;
    }
#pragma unroll
    for (int q = 0; q < 4; q++) {
        float4 wv = *(const float4*)(W + r * 64 + cbase + 4 * q);
        wv.x = f2tf32(wv.x); wv.y = f2tf32(wv.y);
        wv.z = f2tf32(wv.z); wv.w = f2tf32(wv.w);
        *(float4*)&B0[r * SMEM_STRIDE + cbase + 4 * q] = wv;
    }
    __syncthreads();

    // ---- GEMM2: out = relu(node @ W) ----
#pragma unroll
    for (int nt = 0; nt < 4; nt++)
#pragma unroll
        for (int e = 0; e < 4; e++) acc[nt][e] = 0.f;

#pragma unroll
    for (int kk = 0; kk < 8; kk++) {
        const int k = kk * 8;
        uint32_t a[4];
        a[0] = B1u[(i0 + g)     * SMEM_STRIDE + k + tg];
        a[1] = B1u[(i0 + g + 8) * SMEM_STRIDE + k + tg];
        a[2] = B1u[(i0 + g)     * SMEM_STRIDE + k + tg + 4];
        a[3] = B1u[(i0 + g + 8) * SMEM_STRIDE + k + tg + 4];
#pragma unroll
        for (int nt = 0; nt < 4; nt++) {
            uint32_t b[2];
            b[0] = B0u[(k + tg)     * SMEM_STRIDE + j0 + 8 * nt + g];
            b[1] = B0u[(k + tg + 4) * SMEM_STRIDE + j0 + 8 * nt + g];
            mma_tf32(acc[nt], a, b);
        }
    }

    // ---- ReLU + store (float2 per fragment half; 32B-sector aligned) ----
#pragma unroll
    for (int nt = 0; nt < 4; nt++) {
        float2 lo, hi;
        lo.x = fmaxf(acc[nt][0], 0.f); lo.y = fmaxf(acc[nt][1], 0.f);
        hi.x = fmaxf(acc[nt][2], 0.f); hi.y = fmaxf(acc[nt][3], 0.f);
        *(float2*)(Ob + (i0 + g)     * 64 + j0 + 8 * nt + 2 * tg) = lo;
        *(float2*)(Ob + (i0 + g + 8) * 64 + j0 + 8 * nt + 2 * tg) = hi;
    }
}

extern "C" void kernel_launch(void* const* d_in, const int* in_sizes, int n_in,
                              void* d_out, int out_size) {
    const float* X  = (const float*)d_in[0];
    const float* W  = (const float*)d_in[1];
    const float* a2 = (const float*)d_in[2];
    const float* b2 = (const float*)d_in[3];
    float* out = (float*)d_out;

    const int nc = in_sizes[0] / 4096;   // 4096 batch tiles of 64x64
    gnn_fused_kernel<<<nc, 256>>>(X, W, a2, b2, out);
}

// round 8
// speedup vs baseline: 1.7251x; 1.2421x over previous
#include <cuda_runtime.h>
#include <cstdint>

// GNN_82592221102580 — fused per 64x64 batch tile (nc = 4096):
//   E = exp(X); Sinv[i] = 1/sum_k E[k][i]
//   Xn = LayerNorm(X) (ddof=1)
//   node[i][j] = Sinv[i] * sum_k E[k][i]*Xn[k][j]      <- tensor cores (tf32)
//   out = relu(node @ W)                               <- tensor cores (tf32)
// One CTA (256 thr, 8 warps) per tile, mma.sync.m16n8k8 tf32.
// Stride 72 makes every fragment load bank-conflict-free (bank = 8*tg + g,
// all 32 distinct); node is stored TRANSPOSED so GEMM2's A-operand uses the
// same conflict-free column pattern.

#define SMEM_STRIDE 72   // 72 mod 32 = 8 -> col-pattern banks 8*tg+g all distinct

__device__ __forceinline__ float f2tf32(float f) {
    uint32_t o;
    asm("cvt.rna.tf32.f32 %0, %1;" : "=r"(o) : "f"(f));
    return __uint_as_float(o);
}

__device__ __forceinline__ void mma_tf32(float d[4], const uint32_t a[4], const uint32_t b[2]) {
    asm volatile(
        "mma.sync.aligned.m16n8k8.row.col.f32.tf32.tf32.f32 "
        "{%0,%1,%2,%3}, {%4,%5,%6,%7}, {%8,%9}, {%0,%1,%2,%3};"
        : "+f"(d[0]), "+f"(d[1]), "+f"(d[2]), "+f"(d[3])
        : "r"(a[0]), "r"(a[1]), "r"(a[2]), "r"(a[3]), "r"(b[0]), "r"(b[1]));
}

__global__ __launch_bounds__(256) void gnn_fused_kernel(
    const float* __restrict__ X,
    const float* __restrict__ W,
    const float* __restrict__ a2,
    const float* __restrict__ b2,
    float* __restrict__ out)
{
    __shared__ __align__(16) float B0[64 * SMEM_STRIDE]; // Xn (tf32), later W (tf32)
    __shared__ __align__(16) float B1[64 * SMEM_STRIDE]; // E (tf32), later node^T (tf32)
    __shared__ __align__(16) float a2s[64];
    __shared__ __align__(16) float b2s[64];
    __shared__ __align__(16) float Sp[4 * 64];
    __shared__ __align__(16) float Sinv[64];

    const int t = threadIdx.x;
    const float* __restrict__ Xb = X + (size_t)blockIdx.x * 4096u;
    float* __restrict__ Ob = out + (size_t)blockIdx.x * 4096u;

    if (t < 64) { a2s[t] = a2[t]; b2s[t] = b2[t]; }

    // ---- Phase 1: load 16 X elems/thread, E (tf32) -> B1, row stats ----
    const int r     = t >> 2;
    const int part  = t & 3;
    const int cbase = part * 16;

    float4 xv[4];
#pragma unroll
    for (int q = 0; q < 4; q++)
        xv[q] = *(const float4*)(Xb + r * 64 + cbase + 4 * q);

    float s = 0.f, ss = 0.f;
#pragma unroll
    for (int q = 0; q < 4; q++) {
        float4 v = xv[q];
        s  += v.x + v.y + v.z + v.w;
        ss += v.x * v.x + v.y * v.y + v.z * v.z + v.w * v.w;
        float4 e;
        e.x = f2tf32(__expf(v.x)); e.y = f2tf32(__expf(v.y));
        e.z = f2tf32(__expf(v.z)); e.w = f2tf32(__expf(v.w));
        *(float4*)&B1[r * SMEM_STRIDE + cbase + 4 * q] = e;
    }
    s  += __shfl_xor_sync(0xFFFFFFFFu, s, 1);
    s  += __shfl_xor_sync(0xFFFFFFFFu, s, 2);
    ss += __shfl_xor_sync(0xFFFFFFFFu, ss, 1);
    ss += __shfl_xor_sync(0xFFFFFFFFu, ss, 2);

    const float mean = s * (1.0f / 64.0f);
    float var = (ss - 64.0f * mean * mean) * (1.0f / 63.0f);
    var = fmaxf(var, 0.0f);
    const float rinv = 1.0f / (sqrtf(var) + 1e-6f);

    __syncthreads();   // a2s/b2s ready; B1 (E) fully written

    // ---- Xn (tf32) -> B0 ----
#pragma unroll
    for (int q = 0; q < 4; q++) {
        float4 v = xv[q];
        const int j = cbase + 4 * q;
        float4 xn;
        xn.x = f2tf32(a2s[j + 0] * (v.x - mean) * rinv + b2s[j + 0]);
        xn.y = f2tf32(a2s[j + 1] * (v.y - mean) * rinv + b2s[j + 1]);
        xn.z = f2tf32(a2s[j + 2] * (v.z - mean) * rinv + b2s[j + 2]);
        xn.w = f2tf32(a2s[j + 3] * (v.w - mean) * rinv + b2s[j + 3]);
        *(float4*)&B0[r * SMEM_STRIDE + j] = xn;
    }

    // ---- Column sums of E -> Sinv (lanes span 32 consecutive cols: conflict-free) ----
    {
        const int i = t & 63, p = t >> 6;
        float cs = 0.f;
#pragma unroll
        for (int k = 0; k < 16; k++)
            cs += B1[(p * 16 + k) * SMEM_STRIDE + i];
        Sp[p * 64 + i] = cs;
    }
    __syncthreads();
    if (t < 64)
        Sinv[t] = 1.0f / (Sp[t] + Sp[64 + t] + Sp[128 + t] + Sp[192 + t]);
    __syncthreads();

    // ---- Warp tiling: warp w owns rows [16*(w&3), +16), cols [32*(w>>2), +32) ----
    const int warp = t >> 5;
    const int lane = t & 31;
    const int g  = lane >> 2;          // group id  (0..7)
    const int tg = lane & 3;           // thread-in-group (0..3)
    const int i0 = (warp & 3) * 16;
    const int j0 = (warp >> 2) * 32;

    const uint32_t* __restrict__ B0u = (const uint32_t*)B0;
    const uint32_t* __restrict__ B1u = (const uint32_t*)B1;

    float acc[4][4];
#pragma unroll
    for (int nt = 0; nt < 4; nt++)
#pragma unroll
        for (int e = 0; e < 4; e++) acc[nt][e] = 0.f;

    // ---- GEMM1: node_u[i][j] = sum_k E[k][i] * Xn[k][j]  (A-op = E^T col reads) ----
#pragma unroll
    for (int kk = 0; kk < 8; kk++) {
        const int k = kk * 8;
        uint32_t a[4];
        a[0] = B1u[(k + tg)     * SMEM_STRIDE + i0 + g];
        a[1] = B1u[(k + tg)     * SMEM_STRIDE + i0 + g + 8];
        a[2] = B1u[(k + tg + 4) * SMEM_STRIDE + i0 + g];
        a[3] = B1u[(k + tg + 4) * SMEM_STRIDE + i0 + g + 8];
#pragma unroll
        for (int nt = 0; nt < 4; nt++) {
            uint32_t b[2];
            b[0] = B0u[(k + tg)     * SMEM_STRIDE + j0 + 8 * nt + g];
            b[1] = B0u[(k + tg + 4) * SMEM_STRIDE + j0 + 8 * nt + g];
            mma_tf32(acc[nt], a, b);
        }
    }

    // scale rows by Sinv
    const float s0 = Sinv[i0 + g];
    const float s1 = Sinv[i0 + g + 8];

    __syncthreads();   // all reads of E/Xn done; recycle buffers

    // node^T (tf32) -> B1:  nodeT[j][i] = node[i][j]   (GEMM2 A-op becomes col-pattern)
#pragma unroll
    for (int nt = 0; nt < 4; nt++) {
        const int jc = j0 + 8 * nt + 2 * tg;
        B1[(jc)     * SMEM_STRIDE + i0 + g]     = f2tf32(acc[nt][0] * s0);
        B1[(jc + 1) * SMEM_STRIDE + i0 + g]     = f2tf32(acc[nt][1] * s0);
        B1[(jc)     * SMEM_STRIDE + i0 + g + 8] = f2tf32(acc[nt][2] * s1);
        B1[(jc + 1) * SMEM_STRIDE + i0 + g + 8] = f2tf32(acc[nt][3] * s1);
    }
    // W (tf32) -> B0
#pragma unroll
    for (int q = 0; q < 4; q++) {
        float4 wv = *(const float4*)(W + r * 64 + cbase + 4 * q);
        wv.x = f2tf32(wv.x); wv.y = f2tf32(wv.y);
        wv.z = f2tf32(wv.z); wv.w = f2tf32(wv.w);
        *(float4*)&B0[r * SMEM_STRIDE + cbase + 4 * q] = wv;
    }
    __syncthreads();

    // ---- GEMM2: out = relu(node @ W)  (A-op from node^T: col-pattern, conflict-free) ----
#pragma unroll
    for (int nt = 0; nt < 4; nt++)
#pragma unroll
        for (int e = 0; e < 4; e++) acc[nt][e] = 0.f;

#pragma unroll
    for (int kk = 0; kk < 8; kk++) {
        const int k = kk * 8;
        uint32_t a[4];
        a[0] = B1u[(k + tg)     * SMEM_STRIDE + i0 + g];      // node[i0+g][k+tg]
        a[1] = B1u[(k + tg)     * SMEM_STRIDE + i0 + g + 8];
        a[2] = B1u[(k + tg + 4) * SMEM_STRIDE + i0 + g];
        a[3] = B1u[(k + tg + 4) * SMEM_STRIDE + i0 + g + 8];
#pragma unroll
        for (int nt = 0; nt < 4; nt++) {
            uint32_t b[2];
            b[0] = B0u[(k + tg)     * SMEM_STRIDE + j0 + 8 * nt + g];
            b[1] = B0u[(k + tg + 4) * SMEM_STRIDE + j0 + 8 * nt + g];
            mma_tf32(acc[nt], a, b);
        }
    }

    // ---- ReLU + store ----
#pragma unroll
    for (int nt = 0; nt < 4; nt++) {
        float2 lo, hi;
        lo.x = fmaxf(acc[nt][0], 0.f); lo.y = fmaxf(acc[nt][1], 0.f);
        hi.x = fmaxf(acc[nt][2], 0.f); hi.y = fmaxf(acc[nt][3], 0.f);
        *(float2*)(Ob + (i0 + g)     * 64 + j0 + 8 * nt + 2 * tg) = lo;
        *(float2*)(Ob + (i0 + g + 8) * 64 + j0 + 8 * nt + 2 * tg) = hi;
    }
}

extern "C" void kernel_launch(void* const* d_in, const int* in_sizes, int n_in,
                              void* d_out, int out_size) {
    const float* X  = (const float*)d_in[0];
    const float* W  = (const float*)d_in[1];
    const float* a2 = (const float*)d_in[2];
    const float* b2 = (const float*)d_in[3];
    float* out = (float*)d_out;

    const int nc = in_sizes[0] / 4096;   // 4096 batch tiles of 64x64
    gnn_fused_kernel<<<nc, 256>>>(X, W, a2, b2, out);
}

// round 10
// speedup vs baseline: 2.7498x; 1.5940x over previous
#include <cuda_runtime.h>
#include <cuda_fp16.h>
#include <cstdint>

// GNN_82592221102580 — fused per 64x64 batch tile (nc = 4096):
//   E = exp(X); Sinv[i] = 1/sum_k E[k][i]
//   Xn = LayerNorm(X) (ddof=1)
//   node[i][j] = Sinv[i] * sum_k E[k][i]*Xn[k][j]   <- mma.m16n8k16 fp16 (f32 acc)
//   out = relu(node @ W)                            <- mma.m16n8k16 fp16 (f32 acc)
//
// 2 batch tiles per CTA (256 thr). 4 warps per tile, each a 32x32 output tile.
// All MMA operands live in 8KB half2-packed buffers [64 rows][32 k-pairs] with an
// XOR swizzle that is bank-conflict-free for both the packed stores (each thread
// owns two consecutive X rows -> local half2 pack, no shuffles) and all fragment
// read patterns.

__device__ __forceinline__ int swz(int i, int kp) {
    return i * 32 + (kp ^ ((((i >> 3) ^ i) & 7) << 2));
}

// pack (lo, hi) -> u32 with lo in bits[15:0].  PTX: cvt.rn.f16x2.f32 d, a, b
// places operand b in the LOW half, so pass (hi, lo).
__device__ __forceinline__ uint32_t pack_h2(float lo, float hi) {
    uint32_t r;
    asm("cvt.rn.f16x2.f32 %0, %1, %2;" : "=r"(r) : "f"(hi), "f"(lo));
    return r;
}

__device__ __forceinline__ void mma_f16(float d[4], const uint32_t a[4],
                                        uint32_t b0, uint32_t b1) {
    asm volatile(
        "mma.sync.aligned.m16n8k16.row.col.f32.f16.f16.f32 "
        "{%0,%1,%2,%3}, {%4,%5,%6,%7}, {%8,%9}, {%0,%1,%2,%3};"
        : "+f"(d[0]), "+f"(d[1]), "+f"(d[2]), "+f"(d[3])
        : "r"(a[0]), "r"(a[1]), "r"(a[2]), "r"(a[3]), "r"(b0), "r"(b1));
}

// dynamic smem layout (bytes)
#define OF_ET 0          // [2][2048] u32  E^T packed:  ET[i][kp] = (E[2kp][i], E[2kp+1][i])
#define OF_XN 16384      // [2][2048] u32  Xn^T packed: XN[j][kp] = (Xn[2kp][j], ...)
#define OF_ND 32768      // [2][2048] u32  node packed: ND[i][jp] = (node[i][2jp], ...)
#define OF_WT 49152      // [2048]    u32  W^T packed:  WT[j][kp] = (W[2kp][j], ...)
#define OF_SP 57344      // [2][8][64] f32 colsum partials
#define OF_SI 61440      // [2][64]   f32  Sinv
#define OF_A2 61952      // [64] f32
#define OF_B2 62208      // [64] f32
#define SMEM_BYTES 62464

__global__ __launch_bounds__(256) void gnn_fused_kernel(
    const float* __restrict__ X,
    const float* __restrict__ W,
    const float* __restrict__ a2,
    const float* __restrict__ b2,
    float* __restrict__ out)
{
    extern __shared__ __align__(16) char sm[];
    uint32_t* ET = (uint32_t*)(sm + OF_ET);
    uint32_t* XN = (uint32_t*)(sm + OF_XN);
    uint32_t* ND = (uint32_t*)(sm + OF_ND);
    uint32_t* WT = (uint32_t*)(sm + OF_WT);
    float*    Sp = (float*)(sm + OF_SP);
    float*    Si = (float*)(sm + OF_SI);
    float*   a2s = (float*)(sm + OF_A2);
    float*   b2s = (float*)(sm + OF_B2);

    const int t    = threadIdx.x;
    const int warp = t >> 5;
    const int lane = t & 31;
    const int R    = t >> 3;   // row-pair 0..31 (owns X rows 2R, 2R+1)
    const int C    = t & 7;    // col group (cols 4C..4C+3 and 4C+32..4C+35)

    if (t < 64) { a2s[t] = a2[t]; b2s[t] = b2[t]; }

    // ---- W -> WT (packed, swizzled; no stats needed) ----
    {
        float w0[8], w1[8];
        float4 v;
        v = *(const float4*)(W + (2*R)*64     + 4*C); w0[0]=v.x; w0[1]=v.y; w0[2]=v.z; w0[3]=v.w;
        v = *(const float4*)(W + (2*R)*64 +32 + 4*C); w0[4]=v.x; w0[5]=v.y; w0[6]=v.z; w0[7]=v.w;
        v = *(const float4*)(W + (2*R+1)*64   + 4*C); w1[0]=v.x; w1[1]=v.y; w1[2]=v.z; w1[3]=v.w;
        v = *(const float4*)(W + (2*R+1)*64+32+ 4*C); w1[4]=v.x; w1[5]=v.y; w1[6]=v.z; w1[7]=v.w;
#pragma unroll
        for (int q = 0; q < 8; q++) {
            const int c = 4*C + (q & 3) + (q >> 2) * 32;
            WT[swz(c, R)] = pack_h2(w0[q], w1[q]);
        }
    }
    __syncthreads();   // a2s/b2s visible

    // ---- Phase A per tile: X -> E^T, Xn^T (packed) + column-sum partials ----
#pragma unroll
    for (int tile = 0; tile < 2; tile++) {
        const float* Xb = X + (size_t)(2 * blockIdx.x + tile) * 4096u;
        float x0[8], x1[8];
        float4 v;
        v = *(const float4*)(Xb + (2*R)*64      + 4*C); x0[0]=v.x; x0[1]=v.y; x0[2]=v.z; x0[3]=v.w;
        v = *(const float4*)(Xb + (2*R)*64 + 32 + 4*C); x0[4]=v.x; x0[5]=v.y; x0[6]=v.z; x0[7]=v.w;
        v = *(const float4*)(Xb + (2*R+1)*64    + 4*C); x1[0]=v.x; x1[1]=v.y; x1[2]=v.z; x1[3]=v.w;
        v = *(const float4*)(Xb + (2*R+1)*64+32 + 4*C); x1[4]=v.x; x1[5]=v.y; x1[6]=v.z; x1[7]=v.w;

        float s0=0.f, ss0=0.f, s1=0.f, ss1=0.f;
#pragma unroll
        for (int q = 0; q < 8; q++) {
            s0 += x0[q]; ss0 += x0[q]*x0[q];
            s1 += x1[q]; ss1 += x1[q]*x1[q];
        }
#pragma unroll
        for (int m = 1; m <= 4; m <<= 1) {     // 8 lanes share a row-pair
            s0  += __shfl_xor_sync(0xFFFFFFFFu, s0,  m);
            ss0 += __shfl_xor_sync(0xFFFFFFFFu, ss0, m);
            s1  += __shfl_xor_sync(0xFFFFFFFFu, s1,  m);
            ss1 += __shfl_xor_sync(0xFFFFFFFFu, ss1, m);
        }
        const float mean0 = s0 * (1.0f/64.0f);
        const float mean1 = s1 * (1.0f/64.0f);
        float var0 = fmaxf((ss0 - 64.0f*mean0*mean0) * (1.0f/63.0f), 0.0f);
        float var1 = fmaxf((ss1 - 64.0f*mean1*mean1) * (1.0f/63.0f), 0.0f);
        const float rv0 = 1.0f / (sqrtf(var0) + 1e-6f);
        const float rv1 = 1.0f / (sqrtf(var1) + 1e-6f);

        uint32_t* ETt = ET + tile * 2048;
        uint32_t* XNt = XN + tile * 2048;
        float pc[8];
#pragma unroll
        for (int q = 0; q < 8; q++) {
            const int c = 4*C + (q & 3) + (q >> 2) * 32;
            const float e0 = __expf(x0[q]);
            const float e1 = __expf(x1[q]);
            pc[q] = e0 + e1;
            ETt[swz(c, R)] = pack_h2(e0, e1);
            const float n0 = a2s[c] * (x0[q] - mean0) * rv0 + b2s[c];
            const float n1 = a2s[c] * (x1[q] - mean1) * rv1 + b2s[c];
            XNt[swz(c, R)] = pack_h2(n0, n1);
        }
        // column-sum partials: reduce the warp's 4 row-pairs (8 rows)
#pragma unroll
        for (int q = 0; q < 8; q++) {
            pc[q] += __shfl_xor_sync(0xFFFFFFFFu, pc[q], 8);
            pc[q] += __shfl_xor_sync(0xFFFFFFFFu, pc[q], 16);
        }
        if (lane < 8) {
#pragma unroll
            for (int q = 0; q < 8; q++) {
                const int c = 4*lane + (q & 3) + (q >> 2) * 32;
                Sp[tile*512 + warp*64 + c] = pc[q];
            }
        }
    }
    __syncthreads();

    // ---- Sinv ----
    if (t < 128) {
        const int tl = t >> 6, i = t & 63;
        float s = 0.f;
#pragma unroll
        for (int w = 0; w < 8; w++) s += Sp[tl*512 + w*64 + i];
        Si[tl*64 + i] = 1.0f / s;
    }
    __syncthreads();

    // ---- GEMMs: warps 0-3 tile0, 4-7 tile1; each warp a 32x32 output tile ----
    const int tile = warp >> 2;
    const int wq   = warp & 3;
    const int i0w  = (wq & 1) * 32;
    const int j0w  = (wq >> 1) * 32;
    const int g    = lane >> 2;
    const int tg   = lane & 3;

    uint32_t* ETt = ET + tile * 2048;
    uint32_t* XNt = XN + tile * 2048;
    uint32_t* NDt = ND + tile * 2048;

    float acc[2][4][4];
#pragma unroll
    for (int mt = 0; mt < 2; mt++)
#pragma unroll
        for (int nt = 0; nt < 4; nt++)
#pragma unroll
            for (int e = 0; e < 4; e++) acc[mt][nt][e] = 0.f;

    // GEMM1: node_u = E^T @ Xn   (A = ET rows i, B = XN cols j; k packed in pairs)
#pragma unroll
    for (int s = 0; s < 4; s++) {
        uint32_t a[2][4];
#pragma unroll
        for (int mt = 0; mt < 2; mt++) {
            const int i = i0w + 16*mt + g;
            a[mt][0] = ETt[swz(i,     8*s + tg)];
            a[mt][1] = ETt[swz(i + 8, 8*s + tg)];
            a[mt][2] = ETt[swz(i,     8*s + tg + 4)];
            a[mt][3] = ETt[swz(i + 8, 8*s + tg + 4)];
        }
#pragma unroll
        for (int nt = 0; nt < 4; nt++) {
            const int j = j0w + 8*nt + g;
            const uint32_t b0 = XNt[swz(j, 8*s + tg)];
            const uint32_t b1 = XNt[swz(j, 8*s + tg + 4)];
            mma_f16(acc[0][nt], a[0], b0, b1);
            mma_f16(acc[1][nt], a[1], b0, b1);
        }
    }

    // scale rows by Sinv, pack node -> ND
#pragma unroll
    for (int mt = 0; mt < 2; mt++) {
        const int i = i0w + 16*mt + g;
        const float sA = Si[tile*64 + i];
        const float sB = Si[tile*64 + i + 8];
#pragma unroll
        for (int nt = 0; nt < 4; nt++) {
            const int jp = (j0w >> 1) + 4*nt + tg;
            NDt[swz(i,     jp)] = pack_h2(acc[mt][nt][0] * sA, acc[mt][nt][1] * sA);
            NDt[swz(i + 8, jp)] = pack_h2(acc[mt][nt][2] * sB, acc[mt][nt][3] * sB);
        }
    }
    __syncthreads();

    // GEMM2: out = relu(node @ W)   (A = ND rows i, B = WT cols j)
#pragma unroll
    for (int mt = 0; mt < 2; mt++)
#pragma unroll
        for (int nt = 0; nt < 4; nt++)
#pragma unroll
            for (int e = 0; e < 4; e++) acc[mt][nt][e] = 0.f;

#pragma unroll
    for (int s = 0; s < 4; s++) {
        uint32_t a[2][4];
#pragma unroll
        for (int mt = 0; mt < 2; mt++) {
            const int i = i0w + 16*mt + g;
            a[mt][0] = NDt[swz(i,     8*s + tg)];
            a[mt][1] = NDt[swz(i + 8, 8*s + tg)];
            a[mt][2] = NDt[swz(i,     8*s + tg + 4)];
            a[mt][3] = NDt[swz(i + 8, 8*s + tg + 4)];
        }
#pragma unroll
        for (int nt = 0; nt < 4; nt++) {
            const int j = j0w + 8*nt + g;
            const uint32_t b0 = WT[swz(j, 8*s + tg)];
            const uint32_t b1 = WT[swz(j, 8*s + tg + 4)];
            mma_f16(acc[0][nt], a[0], b0, b1);
            mma_f16(acc[1][nt], a[1], b0, b1);
        }
    }

    // ReLU + store
    float* Ob = out + (size_t)(2 * blockIdx.x + tile) * 4096u;
#pragma unroll
    for (int mt = 0; mt < 2; mt++) {
        const int i = i0w + 16*mt + g;
#pragma unroll
        for (int nt = 0; nt < 4; nt++) {
            const int j = j0w + 8*nt + 2*tg;
            float2 lo, hi;
            lo.x = fmaxf(acc[mt][nt][0], 0.f); lo.y = fmaxf(acc[mt][nt][1], 0.f);
            hi.x = fmaxf(acc[mt][nt][2], 0.f); hi.y = fmaxf(acc[mt][nt][3], 0.f);
            *(float2*)(Ob + i*64 + j)       = lo;
            *(float2*)(Ob + (i+8)*64 + j)   = hi;
        }
    }
}

extern "C" void kernel_launch(void* const* d_in, const int* in_sizes, int n_in,
                              void* d_out, int out_size) {
    const float* X  = (const float*)d_in[0];
    const float* W  = (const float*)d_in[1];
    const float* a2 = (const float*)d_in[2];
    const float* b2 = (const float*)d_in[3];
    float* out = (float*)d_out;

    const int nc = in_sizes[0] / 4096;   // 4096 batch tiles of 64x64
    cudaFuncSetAttribute(gnn_fused_kernel, cudaFuncAttributeMaxDynamicSharedMemorySize, SMEM_BYTES);
    gnn_fused_kernel<<<nc / 2, 256, SMEM_BYTES>>>(X, W, a2, b2, out);
}

// round 13
// speedup vs baseline: 3.1721x; 1.1535x over previous
#include <cuda_runtime.h>
#include <cuda_fp16.h>
#include <cstdint>

// GNN_82592221102580 — fused per 64x64 batch tile (nc = 4096):
//   E = exp(X); Sinv[i] = 1/sum_k E[k][i]
//   Xn = LayerNorm(X) (ddof=1)
//   node[i][j] = Sinv[i] * sum_k E[k][i]*Xn[k][j]   <- mma.m16n8k16 fp16 (f32 acc)
//   out = relu(node @ W)                            <- mma.m16n8k16 fp16 (f32 acc)
//
// 2 batch tiles per CTA (256 thr), 4 warps per tile each computing 32x32.
// Operands in half2-packed, XOR-swizzled 8KB buffers; all fragment loads via
// ldmatrix.m8n8.x4. Per-k-step address update: XOR with s<<5 (8 k-pairs = 32B;
// swizzle X occupies kp bits 2-4 so the s field (kp bits 3-4) XORs cleanly).

__device__ __forceinline__ int swz(int i, int kp) {          // word index
    return i * 32 + (kp ^ ((((i >> 3) ^ i) & 7) << 2));
}
__device__ __forceinline__ int swzb(int row, int kp) {       // byte offset
    return row * 128 + 4 * (kp ^ ((((row >> 3) ^ row) & 7) << 2));
}

// pack (lo, hi) -> u32, lo in bits[15:0]. PTX cvt.rn.f16x2.f32 d,a,b puts b low.
__device__ __forceinline__ uint32_t pack_h2(float lo, float hi) {
    uint32_t r;
    asm("cvt.rn.f16x2.f32 %0, %1, %2;" : "=r"(r) : "f"(hi), "f"(lo));
    return r;
}

__device__ __forceinline__ void ldm_x4(uint32_t& r0, uint32_t& r1, uint32_t& r2,
                                       uint32_t& r3, uint32_t addr) {
    asm volatile("ldmatrix.sync.aligned.m8n8.x4.shared.b16 {%0,%1,%2,%3}, [%4];"
                 : "=r"(r0), "=r"(r1), "=r"(r2), "=r"(r3) : "r"(addr));
}

__device__ __forceinline__ void mma_f16(float d[4], const uint32_t a[4],
                                        uint32_t b0, uint32_t b1) {
    asm volatile(
        "mma.sync.aligned.m16n8k16.row.col.f32.f16.f16.f32 "
        "{%0,%1,%2,%3}, {%4,%5,%6,%7}, {%8,%9}, {%0,%1,%2,%3};"
        : "+f"(d[0]), "+f"(d[1]), "+f"(d[2]), "+f"(d[3])
        : "r"(a[0]), "r"(a[1]), "r"(a[2]), "r"(a[3]), "r"(b0), "r"(b1));
}

// dynamic smem layout (bytes)
#define OF_ET 0          // [2][2048] u32  E^T packed:  ET[i][kp]
#define OF_XN 16384      // [2][2048] u32  Xn^T packed: XN[j][kp]
#define OF_ND 32768      // [2][2048] u32  node packed: ND[i][jp]
#define OF_WT 49152      // [2048]    u32  W^T packed:  WT[j][kp]
#define OF_SP 57344      // [2][8][64] f32 colsum partials
#define OF_SI 61440      // [2][64]   f32  Sinv
#define OF_A2 61952      // [64] f32
#define OF_B2 62208      // [64] f32
#define SMEM_BYTES 62464

__global__ __launch_bounds__(256) void gnn_fused_kernel(
    const float* __restrict__ X,
    const float* __restrict__ W,
    const float* __restrict__ a2,
    const float* __restrict__ b2,
    float* __restrict__ out)
{
    extern __shared__ __align__(16) char sm[];
    uint32_t* ET = (uint32_t*)(sm + OF_ET);
    uint32_t* XN = (uint32_t*)(sm + OF_XN);
    uint32_t* ND = (uint32_t*)(sm + OF_ND);
    uint32_t* WT = (uint32_t*)(sm + OF_WT);
    float*    Sp = (float*)(sm + OF_SP);
    float*    Si = (float*)(sm + OF_SI);
    float*   a2s = (float*)(sm + OF_A2);
    float*   b2s = (float*)(sm + OF_B2);

    const uint32_t smb = (uint32_t)__cvta_generic_to_shared(sm);

    const int t    = threadIdx.x;
    const int warp = t >> 5;
    const int lane = t & 31;
    const int R    = t >> 3;   // row-pair 0..31 (owns rows 2R, 2R+1)
    const int C    = t & 7;    // col group (cols 4C..4C+3 and +32)

    if (t < 64) { a2s[t] = a2[t]; b2s[t] = b2[t]; }

    // ---- W -> WT (packed, swizzled) ----
    {
        float w0[8], w1[8];
        float4 v;
        v = *(const float4*)(W + (2*R)*64     + 4*C); w0[0]=v.x; w0[1]=v.y; w0[2]=v.z; w0[3]=v.w;
        v = *(const float4*)(W + (2*R)*64 +32 + 4*C); w0[4]=v.x; w0[5]=v.y; w0[6]=v.z; w0[7]=v.w;
        v = *(const float4*)(W + (2*R+1)*64   + 4*C); w1[0]=v.x; w1[1]=v.y; w1[2]=v.z; w1[3]=v.w;
        v = *(const float4*)(W + (2*R+1)*64+32+ 4*C); w1[4]=v.x; w1[5]=v.y; w1[6]=v.z; w1[7]=v.w;
#pragma unroll
        for (int q = 0; q < 8; q++) {
            const int c = 4*C + (q & 3) + (q >> 2) * 32;
            WT[swz(c, R)] = pack_h2(w0[q], w1[q]);
        }
    }
    __syncthreads();   // a2s/b2s visible

    // ---- Phase A per tile: X -> E^T, Xn^T (packed) + column-sum partials ----
#pragma unroll
    for (int tile = 0; tile < 2; tile++) {
        const float* Xb = X + (size_t)(2 * blockIdx.x + tile) * 4096u;
        float x0[8], x1[8];
        float4 v;
        v = *(const float4*)(Xb + (2*R)*64      + 4*C); x0[0]=v.x; x0[1]=v.y; x0[2]=v.z; x0[3]=v.w;
        v = *(const float4*)(Xb + (2*R)*64 + 32 + 4*C); x0[4]=v.x; x0[5]=v.y; x0[6]=v.z; x0[7]=v.w;
        v = *(const float4*)(Xb + (2*R+1)*64    + 4*C); x1[0]=v.x; x1[1]=v.y; x1[2]=v.z; x1[3]=v.w;
        v = *(const float4*)(Xb + (2*R+1)*64+32 + 4*C); x1[4]=v.x; x1[5]=v.y; x1[6]=v.z; x1[7]=v.w;

        float s0=0.f, ss0=0.f, s1=0.f, ss1=0.f;
#pragma unroll
        for (int q = 0; q < 8; q++) {
            s0 += x0[q]; ss0 += x0[q]*x0[q];
            s1 += x1[q]; ss1 += x1[q]*x1[q];
        }
#pragma unroll
        for (int m = 1; m <= 4; m <<= 1) {
            s0  += __shfl_xor_sync(0xFFFFFFFFu, s0,  m);
            ss0 += __shfl_xor_sync(0xFFFFFFFFu, ss0, m);
            s1  += __shfl_xor_sync(0xFFFFFFFFu, s1,  m);
            ss1 += __shfl_xor_sync(0xFFFFFFFFu, ss1, m);
        }
        const float mean0 = s0 * (1.0f/64.0f);
        const float mean1 = s1 * (1.0f/64.0f);
        float var0 = fmaxf((ss0 - 64.0f*mean0*mean0) * (1.0f/63.0f), 0.0f);
        float var1 = fmaxf((ss1 - 64.0f*mean1*mean1) * (1.0f/63.0f), 0.0f);
        const float rv0 = 1.0f / (sqrtf(var0) + 1e-6f);
        const float rv1 = 1.0f / (sqrtf(var1) + 1e-6f);

        uint32_t* ETt = ET + tile * 2048;
        uint32_t* XNt = XN + tile * 2048;
        float pc[8];
#pragma unroll
        for (int q = 0; q < 8; q++) {
            const int c = 4*C + (q & 3) + (q >> 2) * 32;
            const float e0 = __expf(x0[q]);
            const float e1 = __expf(x1[q]);
            pc[q] = e0 + e1;
            ETt[swz(c, R)] = pack_h2(e0, e1);
            const float n0 = a2s[c] * (x0[q] - mean0) * rv0 + b2s[c];
            const float n1 = a2s[c] * (x1[q] - mean1) * rv1 + b2s[c];
            XNt[swz(c, R)] = pack_h2(n0, n1);
        }
#pragma unroll
        for (int q = 0; q < 8; q++) {
            pc[q] += __shfl_xor_sync(0xFFFFFFFFu, pc[q], 8);
            pc[q] += __shfl_xor_sync(0xFFFFFFFFu, pc[q], 16);
        }
        if (lane < 8) {
#pragma unroll
            for (int q = 0; q < 8; q++) {
                const int c = 4*lane + (q & 3) + (q >> 2) * 32;
                Sp[tile*512 + warp*64 + c] = pc[q];
            }
        }
    }
    __syncthreads();

    // ---- Sinv ----
    if (t < 128) {
        const int tl = t >> 6, i = t & 63;
        float s = 0.f;
#pragma unroll
        for (int w = 0; w < 8; w++) s += Sp[tl*512 + w*64 + i];
        Si[tl*64 + i] = 1.0f / s;
    }
    __syncthreads();

    // ---- GEMMs: warps 0-3 tile0, 4-7 tile1; each warp 32x32 output ----
    const int tile = warp >> 2;
    const int wq   = warp & 3;
    const int i0w  = (wq & 1) * 32;
    const int j0w  = (wq >> 1) * 32;
    const int g    = lane >> 2;
    const int tg   = lane & 3;

    // ldmatrix per-lane addressing: lanes 0-15 -> rows base+(lane&15), kp-block 0;
    // lanes 16-31 -> same rows, kp-block 1 (kb=4).
    const int rl = lane & 15;
    const int kb = (lane >> 4) * 4;

    const uint32_t etB = smb + OF_ET + tile * 8192;
    const uint32_t xnB = smb + OF_XN + tile * 8192;
    const uint32_t ndB = smb + OF_ND + tile * 8192;
    const uint32_t wtB = smb + OF_WT;

    uint32_t adrA[2], adrB[2];
#pragma unroll
    for (int mt = 0; mt < 2; mt++) adrA[mt] = etB + swzb(i0w + 16*mt + rl, kb);
#pragma unroll
    for (int h = 0; h < 2; h++)    adrB[h]  = xnB + swzb(j0w + 16*h + rl, kb);

    float acc[2][4][4];
#pragma unroll
    for (int mt = 0; mt < 2; mt++)
#pragma unroll
        for (int nt = 0; nt < 4; nt++)
#pragma unroll
            for (int e = 0; e < 4; e++) acc[mt][nt][e] = 0.f;

    // GEMM1: node_u = E^T @ Xn
#pragma unroll
    for (int s = 0; s < 4; s++) {
        const uint32_t ax = (uint32_t)(s << 5);   // 8 k-pairs = 32 bytes per step
        uint32_t a[2][4];
#pragma unroll
        for (int mt = 0; mt < 2; mt++)
            ldm_x4(a[mt][0], a[mt][1], a[mt][2], a[mt][3], adrA[mt] ^ ax);
#pragma unroll
        for (int h = 0; h < 2; h++) {
            uint32_t b00, b01, b10, b11;   // (nt=2h k-lo), (2h+1 k-lo), (2h k-hi), (2h+1 k-hi)
            ldm_x4(b00, b01, b10, b11, adrB[h] ^ ax);
            mma_f16(acc[0][2*h],     a[0], b00, b10);
            mma_f16(acc[1][2*h],     a[1], b00, b10);
            mma_f16(acc[0][2*h + 1], a[0], b01, b11);
            mma_f16(acc[1][2*h + 1], a[1], b01, b11);
        }
    }

    // scale rows by Sinv, pack node -> ND
#pragma unroll
    for (int mt = 0; mt < 2; mt++) {
        const int i = i0w + 16*mt + g;
        const float sA = Si[tile*64 + i];
        const float sB = Si[tile*64 + i + 8];
#pragma unroll
        for (int nt = 0; nt < 4; nt++) {
            const int jp = (j0w >> 1) + 4*nt + tg;
            ND[tile*2048 + swz(i,     jp)] = pack_h2(acc[mt][nt][0] * sA, acc[mt][nt][1] * sA);
            ND[tile*2048 + swz(i + 8, jp)] = pack_h2(acc[mt][nt][2] * sB, acc[mt][nt][3] * sB);
        }
    }
    __syncthreads();

    // GEMM2: out = relu(node @ W)
#pragma unroll
    for (int mt = 0; mt < 2; mt++) adrA[mt] = ndB + swzb(i0w + 16*mt + rl, kb);
#pragma unroll
    for (int h = 0; h < 2; h++)    adrB[h]  = wtB + swzb(j0w + 16*h + rl, kb);

#pragma unroll
    for (int mt = 0; mt < 2; mt++)
#pragma unroll
        for (int nt = 0; nt < 4; nt++)
#pragma unroll
            for (int e = 0; e < 4; e++) acc[mt][nt][e] = 0.f;

#pragma unroll
    for (int s = 0; s < 4; s++) {
        const uint32_t ax = (uint32_t)(s << 5);
        uint32_t a[2][4];
#pragma unroll
        for (int mt = 0; mt < 2; mt++)
            ldm_x4(a[mt][0], a[mt][1], a[mt][2], a[mt][3], adrA[mt] ^ ax);
#pragma unroll
        for (int h = 0; h < 2; h++) {
            uint32_t b00, b01, b10, b11;
            ldm_x4(b00, b01, b10, b11, adrB[h] ^ ax);
            mma_f16(acc[0][2*h],     a[0], b00, b10);
            mma_f16(acc[1][2*h],     a[1], b00, b10);
            mma_f16(acc[0][2*h + 1], a[0], b01, b11);
            mma_f16(acc[1][2*h + 1], a[1], b01, b11);
        }
    }

    // ReLU + store
    float* Ob = out + (size_t)(2 * blockIdx.x + tile) * 4096u;
#pragma unroll
    for (int mt = 0; mt < 2; mt++) {
        const int i = i0w + 16*mt + g;
#pragma unroll
        for (int nt = 0; nt < 4; nt++) {
            const int j = j0w + 8*nt + 2*tg;
            float2 lo, hi;
            lo.x = fmaxf(acc[mt][nt][0], 0.f); lo.y = fmaxf(acc[mt][nt][1], 0.f);
            hi.x = fmaxf(acc[mt][nt][2], 0.f); hi.y = fmaxf(acc[mt][nt][3], 0.f);
            *(float2*)(Ob + i*64 + j)     = lo;
            *(float2*)(Ob + (i+8)*64 + j) = hi;
        }
    }
}

extern "C" void kernel_launch(void* const* d_in, const int* in_sizes, int n_in,
                              void* d_out, int out_size) {
    const float* X  = (const float*)d_in[0];
    const float* W  = (const float*)d_in[1];
    const float* a2 = (const float*)d_in[2];
    const float* b2 = (const float*)d_in[3];
    float* out = (float*)d_out;

    const int nc = in_sizes[0] / 4096;   // 4096 batch tiles of 64x64
    cudaFuncSetAttribute(gnn_fused_kernel, cudaFuncAttributeMaxDynamicSharedMemorySize, SMEM_BYTES);
    gnn_fused_kernel<<<nc / 2, 256, SMEM_BYTES>>>(X, W, a2, b2, out);
}